// round 8
// baseline (speedup 1.0000x reference)
#include <cuda_runtime.h>
#include <cuda_fp16.h>
#include <cstdint>

#define BB 4
#define NNN 2048
#define KK 30
#define NNODE (BB*NNN)        // 8192
#define NEDGE (NNODE*KK)      // 245760
#define EPB 128               // edges (M) per k_edge block
#define NCH 13                // K chunks of 32 (K = 416)
#define ROWB 80               // smem row stride in bytes (40 halves)
#define KEYMAX 0xFFFFFFFFFFFFFFFFull

typedef unsigned long long ull;
typedef unsigned int uint;

// scratch: __device__ globals (allocation-free rule)
__device__ float g_coords5[NNODE*15];   // N,Ca,C,O,Cb xyz per node
__device__ float g_ca[NNODE*3];
__device__ int   g_eidx[NEDGE];
__device__ __align__(16) __half g_wt[128*416];   // W^T fp16: [n][k]

// pair table: atom of node i, atom of neighbor j; N=0,Ca=1,C=2,O=3,Cb=4
__constant__ int c_pa[25] = {1, 0,2,3,4, 1,1,1,1, 0,0,0, 4,4, 3, 0,2,3,4, 2,3,4, 2,3, 2};
__constant__ int c_pb[25] = {1, 0,2,3,4, 0,2,3,4, 2,3,4, 2,3, 2, 1,1,1,1, 0,0,0, 4,4, 3};

#define RBF_DEL 1.33333333333f   // (22-2)/15
#define RBF_INVS 0.8f            // 1/sigma, sigma = 1.25

// ---------------------------------------------------------------- helpers
__device__ __forceinline__ void mma16(float* d, const uint* a, const uint* b){
    asm volatile("mma.sync.aligned.m16n8k16.row.col.f32.f16.f16.f32 "
        "{%0,%1,%2,%3}, {%4,%5,%6,%7}, {%8,%9}, {%0,%1,%2,%3};"
        : "+f"(d[0]), "+f"(d[1]), "+f"(d[2]), "+f"(d[3])
        : "r"(a[0]), "r"(a[1]), "r"(a[2]), "r"(a[3]), "r"(b[0]), "r"(b[1]));
}
__device__ __forceinline__ void ldmx4(uint* r, uint addr){
    asm volatile("ldmatrix.sync.aligned.m8n8.x4.shared.b16 {%0,%1,%2,%3}, [%4];"
        : "=r"(r[0]), "=r"(r[1]), "=r"(r[2]), "=r"(r[3]) : "r"(addr));
}
__device__ __forceinline__ void cp16(uint saddr, const void* g){
    asm volatile("cp.async.cg.shared.global [%0], [%1], 16;" :: "r"(saddr), "l"(g));
}
#define CP_COMMIT() asm volatile("cp.async.commit_group;" ::: "memory")
#define CP_WAIT0()  asm volatile("cp.async.wait_group 0;" ::: "memory")

__device__ __forceinline__ ull shfl_xor_u64(ull v, int m){
    uint lo = (uint)v, hi = (uint)(v >> 32);
    lo = __shfl_xor_sync(0xFFFFFFFFu, lo, m);
    hi = __shfl_xor_sync(0xFFFFFFFFu, hi, m);
    return ((ull)hi << 32) | lo;
}

// ---------------------------------------------------------------- k_init
// fused: (a) coordinate prep + virtual Cb (gid < NNODE)
//        (b) W^T fp16 transpose (idx < 416*128)
__global__ void k_init(const float* __restrict__ X, const float* __restrict__ We)
{
    int idx = blockIdx.x * blockDim.x + threadIdx.x;
    if (idx < 416*128) {
        int n = idx / 416, k = idx - n*416;
        g_wt[idx] = __float2half(We[k*128 + n]);
    }
    if (idx < NNODE) {
        const float* x = X + idx*12;
        float Nx=x[0],  Ny=x[1],  Nz=x[2];
        float Cax=x[3], Cay=x[4], Caz=x[5];
        float Cx=x[6],  Cy=x[7],  Cz=x[8];
        float Ox=x[9],  Oy=x[10], Oz=x[11];
        float bx=Cax-Nx, by=Cay-Ny, bz=Caz-Nz;
        float cx=Cx-Cax, cy=Cy-Cay, cz=Cz-Caz;
        float ax = by*cz - bz*cy;
        float ay = bz*cx - bx*cz;
        float az = bx*cy - by*cx;
        float Cbx = -0.58273431f*ax + 0.56802827f*bx - 0.54067466f*cx + Cax;
        float Cby = -0.58273431f*ay + 0.56802827f*by - 0.54067466f*cy + Cay;
        float Cbz = -0.58273431f*az + 0.56802827f*bz - 0.54067466f*cz + Caz;
        float* o = g_coords5 + idx*15;
        o[0]=Nx;   o[1]=Ny;   o[2]=Nz;
        o[3]=Cax;  o[4]=Cay;  o[5]=Caz;
        o[6]=Cx;   o[7]=Cy;   o[8]=Cz;
        o[9]=Ox;   o[10]=Oy;  o[11]=Oz;
        o[12]=Cbx; o[13]=Cby; o[14]=Cbz;
        g_ca[idx*3+0]=Cax; g_ca[idx*3+1]=Cay; g_ca[idx*3+2]=Caz;
    }
}

// ---------------------------------------------------------------- k_topk
// exact ascending top-30, fully register-resident keys.
// Phase A: each warp extracts its own top-30 from its 256 keys (no barriers).
// Phase B: warp 0 merges the 8x30 candidates.
__global__ void __launch_bounds__(256) k_topk(
    const float* __restrict__ mask,
    float* __restrict__ out_tail,
    int write_tail)
{
    __shared__ float fred[8];
    __shared__ ull   s_c[8*KK];

    int gid = blockIdx.x;
    int b   = gid >> 11;
    int tid = threadIdx.x;
    int lid = tid & 31, wid = tid >> 5;

    float cix = g_ca[gid*3+0], ciy = g_ca[gid*3+1], ciz = g_ca[gid*3+2];
    float mi  = mask[gid];
    const float* cab = g_ca + (size_t)(b << 11) * 3;
    const float* mb  = mask + (b << 11);

    // pass 1: distances into registers
    ull   key[8];
    float m2r[8];
    float lmax = 0.f;
    #pragma unroll
    for (int r = 0; r < 8; r++) {
        int j = tid + (r << 8);
        float dx = cab[j*3+0]-cix, dy = cab[j*3+1]-ciy, dz = cab[j*3+2]-ciz;
        float m2 = mi * mb[j];
        float D  = m2 * __fsqrt_rn(dx*dx + dy*dy + dz*dz + 1e-6f);
        key[r] = ((ull)__float_as_uint(D) << 32) | (unsigned)j;
        m2r[r] = m2;
        lmax = fmaxf(lmax, D);
    }
    #pragma unroll
    for (int m = 16; m > 0; m >>= 1)
        lmax = fmaxf(lmax, __shfl_xor_sync(0xFFFFFFFFu, lmax, m));
    if (lid == 0) fred[wid] = lmax;
    __syncthreads();
    float Dmax = fred[0];
    #pragma unroll
    for (int w = 1; w < 8; w++) Dmax = fmaxf(Dmax, fred[w]);

    // adjust (no-op when mask==1)
    #pragma unroll
    for (int r = 0; r < 8; r++) {
        if (m2r[r] != 1.0f) {
            float D  = __uint_as_float((unsigned)(key[r] >> 32));
            float Da = D + (1.0f - m2r[r]) * Dmax;
            key[r] = ((ull)__float_as_uint(Da) << 32) | (key[r] & 0xFFFFFFFFull);
        }
    }

    // Phase A: warp-local top-30 (barrier-free)
    #pragma unroll 1
    for (int k = 0; k < KK; k++) {
        ull lm = key[0];
        #pragma unroll
        for (int r = 1; r < 8; r++) lm = (key[r] < lm) ? key[r] : lm;
        #pragma unroll
        for (int m = 16; m > 0; m >>= 1) {
            ull o = shfl_xor_u64(lm, m);
            lm = (o < lm) ? o : lm;
        }
        // lm == warp min on all lanes; invalidate the unique holder
        #pragma unroll
        for (int r = 0; r < 8; r++)
            if (key[r] == lm) key[r] = KEYMAX;
        if (lid == 0) s_c[wid*KK + k] = lm;
    }
    __syncthreads();

    // Phase B: warp 0 merges 240 candidates
    if (wid == 0) {
        ull c[8];
        #pragma unroll
        for (int r = 0; r < 8; r++) {
            int idx = lid + (r << 5);
            c[r] = (idx < 8*KK) ? s_c[idx] : KEYMAX;
        }
        #pragma unroll 1
        for (int k = 0; k < KK; k++) {
            ull lm = c[0];
            #pragma unroll
            for (int r = 1; r < 8; r++) lm = (c[r] < lm) ? c[r] : lm;
            #pragma unroll
            for (int m = 16; m > 0; m >>= 1) {
                ull o = shfl_xor_u64(lm, m);
                lm = (o < lm) ? o : lm;
            }
            #pragma unroll
            for (int r = 0; r < 8; r++)
                if (c[r] == lm) c[r] = KEYMAX;
            if (lid == 0) {
                int bj = (int)(lm & 0xFFFFFFFFull);
                g_eidx[gid*KK + k] = bj;
                if (write_tail) out_tail[gid*KK + k] = (float)bj;
            }
        }
    }
}

// ---------------------------------------------------------------- k_edge
// D[128 edges,128 ch] = A[128,416] * W^T[128,416], fp16 mma.sync m16n8k16,
// ldmatrix frags, cp.async double-buffered B, pipelined A-gen, fused LN.
extern __shared__ __align__(16) char sm_raw[];

__global__ void __launch_bounds__(256, 2) k_edge(
    const int*   __restrict__ ridx,
    const int*   __restrict__ chain,
    const float* __restrict__ Wp,
    const float* __restrict__ bp,
    const float* __restrict__ lns,
    const float* __restrict__ lno,
    float*       __restrict__ out)
{
    __shared__ int   s_gi[EPB], s_gj[EPB], s_dp[EPB];
    __shared__ float s_lns[128], s_lno[128], s_bp[16];

    int tid = threadIdx.x, wid = tid >> 5, lid = tid & 31;
    int e0  = blockIdx.x * EPB;

    uint sb = (uint)__cvta_generic_to_shared(sm_raw);
    uint Aoff[2] = { sb,           sb + 10240 };
    uint Boff[2] = { sb + 20480,   sb + 30720 };

    if (tid < EPB) {
        int edge = e0 + tid;
        int node = edge / KK;
        int bb   = node >> 11;
        int gj   = (bb << 11) + g_eidx[edge];
        s_gi[tid] = node; s_gj[tid] = gj;
        int off = ridx[node] - ridx[gj];
        s_dp[tid] = (chain[node] == chain[gj]) ? min(max(off + 32, 0), 64) : 65;
        s_lns[tid] = lns[tid]; s_lno[tid] = lno[tid];
        if (tid < 16) s_bp[tid] = bp[tid];
    }
    __syncthreads();

    int fe  = tid >> 1;     // feature row (edge)
    int fbl = tid & 1;      // 16-half half of the 32-wide chunk

    auto gen_A = [&](int c, int buf) {
        half2* dst = (half2*)(sm_raw + (buf ? 10240 : 0) + fe*ROWB + fbl*32);
        int fb = 2*c + fbl;
        if (fb == 0) {
            const float* wrow = Wp + s_dp[fe]*16;
            #pragma unroll
            for (int jj = 0; jj < 8; jj++)
                dst[jj] = __floats2half2_rn(wrow[2*jj] + s_bp[2*jj],
                                            wrow[2*jj+1] + s_bp[2*jj+1]);
        } else {
            int p = fb - 1;
            const float* pa = g_coords5 + s_gi[fe]*15 + c_pa[p]*3;
            const float* pq = g_coords5 + s_gj[fe]*15 + c_pb[p]*3;
            float dx = pa[0]-pq[0], dy = pa[1]-pq[1], dz = pa[2]-pq[2];
            float d  = __fsqrt_rn(dx*dx + dy*dy + dz*dz + 1e-6f);
            #pragma unroll
            for (int jj = 0; jj < 8; jj++) {
                float u0 = (d - (2.0f + RBF_DEL*(float)(2*jj)))   * RBF_INVS;
                float u1 = (d - (2.0f + RBF_DEL*(float)(2*jj+1))) * RBF_INVS;
                dst[jj] = __floats2half2_rn(__expf(-u0*u0), __expf(-u1*u1));
            }
        }
    };
    auto stage_B = [&](int c, int buf) {
        const char* gb = (const char*)g_wt;
        #pragma unroll
        for (int q = 0; q < 2; q++) {
            int f = tid*2 + q;
            int row = f >> 2, seg = f & 3;
            cp16(Boff[buf] + row*ROWB + seg*16, gb + row*832 + c*64 + seg*16);
        }
        CP_COMMIT();
    };

    int mw = wid >> 1, nw = wid & 1;
    int m0 = mw << 5, n0 = nw << 6;

    int arA = (lid & 7) + ((lid >> 3) & 1) * 8;
    int caA = ((lid >> 4) & 1) * 16;
    int arB = (lid & 7) + ((lid >> 4) & 1) * 8;
    int caB = ((lid >> 3) & 1) * 16;

    float acc[2][8][4];
    #pragma unroll
    for (int mt = 0; mt < 2; mt++)
        #pragma unroll
        for (int nt = 0; nt < 8; nt++)
            #pragma unroll
            for (int q = 0; q < 4; q++) acc[mt][nt][q] = 0.f;

    stage_B(0, 0);
    gen_A(0, 0);
    CP_WAIT0();
    __syncthreads();

    for (int c = 0; c < NCH; ++c) {
        int buf = c & 1, nbuf = buf ^ 1;
        if (c + 1 < NCH) stage_B(c + 1, nbuf);

        #pragma unroll
        for (int ks = 0; ks < 2; ks++) {
            int kb = ks * 32;
            uint a[2][4];
            #pragma unroll
            for (int mt = 0; mt < 2; mt++)
                ldmx4(a[mt], Aoff[buf] + (uint)(m0 + 16*mt + arA)*ROWB + caA + kb);
            uint bf[8][2];
            #pragma unroll
            for (int ntp = 0; ntp < 4; ntp++) {
                uint r[4];
                ldmx4(r, Boff[buf] + (uint)(n0 + 16*ntp + arB)*ROWB + caB + kb);
                bf[2*ntp][0]   = r[0]; bf[2*ntp][1]   = r[1];
                bf[2*ntp+1][0] = r[2]; bf[2*ntp+1][1] = r[3];
            }
            #pragma unroll
            for (int mt = 0; mt < 2; mt++)
                #pragma unroll
                for (int nt = 0; nt < 8; nt++)
                    mma16(acc[mt][nt], a[mt], bf[nt]);
        }

        if (c + 1 < NCH) gen_A(c + 1, nbuf);
        CP_WAIT0();
        __syncthreads();
    }

    // fused LayerNorm epilogue
    int lg = lid >> 2, lt = lid & 3;
    float2* red = (float2*)sm_raw;
    #pragma unroll
    for (int mt = 0; mt < 2; mt++) {
        #pragma unroll
        for (int hf = 0; hf < 2; hf++) {
            float s1 = 0.f, s2 = 0.f;
            #pragma unroll
            for (int nt = 0; nt < 8; nt++) {
                float v0 = acc[mt][nt][2*hf], v1 = acc[mt][nt][2*hf+1];
                s1 += v0 + v1; s2 += v0*v0 + v1*v1;
            }
            #pragma unroll
            for (int m = 1; m < 4; m <<= 1) {
                s1 += __shfl_xor_sync(0xFFFFFFFFu, s1, m);
                s2 += __shfl_xor_sync(0xFFFFFFFFu, s2, m);
            }
            if (lt == 0) {
                int row = m0 + 16*mt + 8*hf + lg;
                red[row*2 + nw] = make_float2(s1, s2);
            }
        }
    }
    __syncthreads();

    #pragma unroll
    for (int mt = 0; mt < 2; mt++) {
        #pragma unroll
        for (int hf = 0; hf < 2; hf++) {
            int row = m0 + 16*mt + 8*hf + lg;
            float2 r0 = red[row*2 + 0], r1 = red[row*2 + 1];
            float s1 = r0.x + r1.x, s2 = r0.y + r1.y;
            float mean = s1 * (1.0f/128.0f);
            float var  = s2 * (1.0f/128.0f) - mean*mean;
            float rstd = rsqrtf(var + 1e-5f);
            float* orow = out + (size_t)(e0 + row) * 128;
            #pragma unroll
            for (int nt = 0; nt < 8; nt++) {
                int col = n0 + nt*8 + 2*lt;
                float v0 = acc[mt][nt][2*hf], v1 = acc[mt][nt][2*hf+1];
                float2 o;
                o.x = (v0 - mean)*rstd*s_lns[col]   + s_lno[col];
                o.y = (v1 - mean)*rstd*s_lns[col+1] + s_lno[col+1];
                *(float2*)(orow + col) = o;
            }
        }
    }
}

// ----------------------------------------------------------------
extern "C" void kernel_launch(void* const* d_in, const int* in_sizes, int n_in,
                              void* d_out, int out_size)
{
    const float* X      = (const float*)d_in[0];
    const float* mask   = (const float*)d_in[1];
    const int*   ridx   = (const int*)  d_in[2];
    const int*   chain  = (const int*)  d_in[3];
    const float* W_pos  = (const float*)d_in[4];
    const float* b_pos  = (const float*)d_in[5];
    const float* W_edge = (const float*)d_in[6];
    const float* ln_s   = (const float*)d_in[7];
    const float* ln_o   = (const float*)d_in[8];
    float* out = (float*)d_out;

    int write_tail = (out_size > NEDGE*128) ? 1 : 0;
    float* tail = out + (size_t)NEDGE*128;

    int smem_bytes = 4 * 128 * ROWB;   // 40960 B

    k_init<<<(416*128 + 255)/256, 256>>>(X, W_edge);
    k_topk<<<NNODE, 256>>>(mask, tail, write_tail);
    k_edge<<<NEDGE/EPB, 256, smem_bytes>>>(ridx, chain, W_pos, b_pos,
                                           ln_s, ln_o, out);
}

// round 9
// speedup vs baseline: 2.2883x; 2.2883x over previous
#include <cuda_runtime.h>
#include <cuda_fp16.h>
#include <cstdint>

#define BB 4
#define NNN 2048
#define KK 30
#define NNODE (BB*NNN)        // 8192
#define NEDGE (NNODE*KK)      // 245760
#define EPB 128               // edges (M) per k_edge block
#define NCH 13                // K chunks of 32 (K = 416)
#define ROWB 80               // smem row stride in bytes (40 halves)
#define KEYMAX 0xFFFFFFFFFFFFFFFFull
#define NCAND 128

typedef unsigned long long ull;
typedef unsigned int uint;

// scratch: __device__ globals (allocation-free rule)
__device__ float g_coords5[NNODE*15];   // N,Ca,C,O,Cb xyz per node
__device__ float g_ca[NNODE*3];
__device__ int   g_eidx[NEDGE];
__device__ __align__(16) __half g_wt[128*416];   // W^T fp16: [n][k]

// pair table: atom of node i, atom of neighbor j; N=0,Ca=1,C=2,O=3,Cb=4
__constant__ int c_pa[25] = {1, 0,2,3,4, 1,1,1,1, 0,0,0, 4,4, 3, 0,2,3,4, 2,3,4, 2,3, 2};
__constant__ int c_pb[25] = {1, 0,2,3,4, 0,2,3,4, 2,3,4, 2,3, 2, 1,1,1,1, 0,0,0, 4,4, 3};

#define RBF_DEL 1.33333333333f   // (22-2)/15
#define RBF_INVS 0.8f            // 1/sigma, sigma = 1.25

// ---------------------------------------------------------------- helpers
__device__ __forceinline__ void mma16(float* d, const uint* a, const uint* b){
    asm volatile("mma.sync.aligned.m16n8k16.row.col.f32.f16.f16.f32 "
        "{%0,%1,%2,%3}, {%4,%5,%6,%7}, {%8,%9}, {%0,%1,%2,%3};"
        : "+f"(d[0]), "+f"(d[1]), "+f"(d[2]), "+f"(d[3])
        : "r"(a[0]), "r"(a[1]), "r"(a[2]), "r"(a[3]), "r"(b[0]), "r"(b[1]));
}
__device__ __forceinline__ void ldmx4(uint* r, uint addr){
    asm volatile("ldmatrix.sync.aligned.m8n8.x4.shared.b16 {%0,%1,%2,%3}, [%4];"
        : "=r"(r[0]), "=r"(r[1]), "=r"(r[2]), "=r"(r[3]) : "r"(addr));
}
__device__ __forceinline__ void cp16(uint saddr, const void* g){
    asm volatile("cp.async.cg.shared.global [%0], [%1], 16;" :: "r"(saddr), "l"(g));
}
#define CP_COMMIT() asm volatile("cp.async.commit_group;" ::: "memory")
#define CP_WAIT0()  asm volatile("cp.async.wait_group 0;" ::: "memory")

__device__ __forceinline__ ull shfl_xor_u64(ull v, int m){
    uint lo = (uint)v, hi = (uint)(v >> 32);
    lo = __shfl_xor_sync(0xFFFFFFFFu, lo, m);
    hi = __shfl_xor_sync(0xFFFFFFFFu, hi, m);
    return ((ull)hi << 32) | lo;
}

// ---------------------------------------------------------------- k_init
// fused: (a) coordinate prep + virtual Cb (idx < NNODE)
//        (b) W^T fp16 transpose (idx < 416*128)
__global__ void k_init(const float* __restrict__ X, const float* __restrict__ We)
{
    int idx = blockIdx.x * blockDim.x + threadIdx.x;
    if (idx < 416*128) {
        int n = idx / 416, k = idx - n*416;
        g_wt[idx] = __float2half(We[k*128 + n]);
    }
    if (idx < NNODE) {
        const float* x = X + idx*12;
        float Nx=x[0],  Ny=x[1],  Nz=x[2];
        float Cax=x[3], Cay=x[4], Caz=x[5];
        float Cx=x[6],  Cy=x[7],  Cz=x[8];
        float Ox=x[9],  Oy=x[10], Oz=x[11];
        float bx=Cax-Nx, by=Cay-Ny, bz=Caz-Nz;
        float cx=Cx-Cax, cy=Cy-Cay, cz=Cz-Caz;
        float ax = by*cz - bz*cy;
        float ay = bz*cx - bx*cz;
        float az = bx*cy - by*cx;
        float Cbx = -0.58273431f*ax + 0.56802827f*bx - 0.54067466f*cx + Cax;
        float Cby = -0.58273431f*ay + 0.56802827f*by - 0.54067466f*cy + Cay;
        float Cbz = -0.58273431f*az + 0.56802827f*bz - 0.54067466f*cz + Caz;
        float* o = g_coords5 + idx*15;
        o[0]=Nx;   o[1]=Ny;   o[2]=Nz;
        o[3]=Cax;  o[4]=Cay;  o[5]=Caz;
        o[6]=Cx;   o[7]=Cy;   o[8]=Cz;
        o[9]=Ox;   o[10]=Oy;  o[11]=Oz;
        o[12]=Cbx; o[13]=Cby; o[14]=Cbz;
        g_ca[idx*3+0]=Cax; g_ca[idx*3+1]=Cay; g_ca[idx*3+2]=Caz;
    }
}

// ---------------------------------------------------------------- k_topk
// exact ascending top-30 via linear-histogram radix-select + rank finish.
__global__ void __launch_bounds__(256) k_topk(
    const float* __restrict__ mask,
    float* __restrict__ out_tail,
    int write_tail)
{
    __shared__ ull   keys[NNN];        // 16 KB
    __shared__ uint  s_hist[1024];     // 4 KB
    __shared__ ull   s_cand[NCAND];    // 1 KB
    __shared__ float fred[8];
    __shared__ uint  s_wtot[8], s_wex[8];
    __shared__ int   s_B, s_before, s_cnt;

    int gid = blockIdx.x;
    int b   = gid >> 11;
    int tid = threadIdx.x;
    int lid = tid & 31, wid = tid >> 5;

    float cix = g_ca[gid*3+0], ciy = g_ca[gid*3+1], ciz = g_ca[gid*3+2];
    float mi  = mask[gid];
    const float* cab = g_ca + (size_t)(b << 11) * 3;
    const float* mb  = mask + (b << 11);

    // zero histogram + counters
    #pragma unroll
    for (int r = 0; r < 4; r++) s_hist[tid + (r << 8)] = 0;
    if (tid < NCAND) s_cand[tid] = KEYMAX;
    if (tid == 0) s_cnt = 0;

    // pass 1: distances (masked), keep keys + m2 in regs, row max
    ull   key[8];
    float m2r[8];
    float lmax = 0.f;
    #pragma unroll
    for (int r = 0; r < 8; r++) {
        int j = tid + (r << 8);
        float dx = cab[j*3+0]-cix, dy = cab[j*3+1]-ciy, dz = cab[j*3+2]-ciz;
        float m2 = mi * mb[j];
        float D  = m2 * __fsqrt_rn(dx*dx + dy*dy + dz*dz + 1e-6f);
        key[r] = ((ull)__float_as_uint(D) << 32) | (unsigned)j;
        m2r[r] = m2;
        lmax = fmaxf(lmax, D);
    }
    #pragma unroll
    for (int m = 16; m > 0; m >>= 1)
        lmax = fmaxf(lmax, __shfl_xor_sync(0xFFFFFFFFu, lmax, m));
    if (lid == 0) fred[wid] = lmax;
    __syncthreads();
    float Dmax = fred[0];
    #pragma unroll
    for (int w = 1; w < 8; w++) Dmax = fmaxf(Dmax, fred[w]);

    // pass 2: mask adjust, store keys, histogram on linear bins
    uint binr[8];
    #pragma unroll
    for (int r = 0; r < 8; r++) {
        float D = __uint_as_float((unsigned)(key[r] >> 32));
        if (m2r[r] != 1.0f) {
            D = D + (1.0f - m2r[r]) * Dmax;
            key[r] = ((ull)__float_as_uint(D) << 32) | (key[r] & 0xFFFFFFFFull);
        }
        keys[tid + (r << 8)] = key[r];
        uint bn = (uint)fminf(D * 25.6f, 1023.0f);
        binr[r] = bn;
        atomicAdd(&s_hist[bn], 1u);
    }
    __syncthreads();

    // block scan over 1024 bins -> find bin B where cum count crosses KK
    uint c4[4];
    #pragma unroll
    for (int i = 0; i < 4; i++) c4[i] = s_hist[tid*4 + i];
    uint s = c4[0] + c4[1] + c4[2] + c4[3];
    uint inc = s;
    #pragma unroll
    for (int m = 1; m < 32; m <<= 1) {
        uint o = __shfl_up_sync(0xFFFFFFFFu, inc, m);
        if (lid >= m) inc += o;
    }
    if (lid == 31) s_wtot[wid] = inc;
    __syncthreads();
    if (tid == 0) {
        uint ex = 0;
        #pragma unroll
        for (int w = 0; w < 8; w++) { s_wex[w] = ex; ex += s_wtot[w]; }
    }
    __syncthreads();
    {
        uint ex = s_wex[wid] + (inc - s);   // exclusive prefix for this thread
        if (ex < KK && ex + s >= KK) {
            uint cum = ex;
            #pragma unroll
            for (int i = 0; i < 4; i++) {
                if (cum + c4[i] >= KK) { s_B = tid*4 + i; s_before = (int)cum; break; }
                cum += c4[i];
            }
        }
    }
    __syncthreads();
    int B = s_B;

    // compaction: candidates = keys with bin <= B
    #pragma unroll
    for (int r = 0; r < 8; r++) {
        if ((int)binr[r] <= B) {
            int pos = atomicAdd(&s_cnt, 1);
            if (pos < NCAND) s_cand[pos] = key[r];
        }
    }
    __syncthreads();

    if (s_cnt <= NCAND) {
        // rank-select finish: 128 threads, each ranks one candidate
        if (tid < NCAND) {
            ull x = s_cand[tid];
            if (x != KEYMAX) {
                int rank = 0;
                for (int j = 0; j < NCAND; j++)
                    rank += (s_cand[j] < x) ? 1 : 0;
                if (rank < KK) {
                    int bj = (int)(x & 0xFFFFFFFFull);
                    g_eidx[gid*KK + rank] = bj;
                    if (write_tail) out_tail[gid*KK + rank] = (float)bj;
                }
            }
        }
    } else {
        // fallback (pathological tie overflow): warp 0 serial extraction
        if (wid == 0) {
            for (int k = 0; k < KK; k++) {
                ull lm = KEYMAX;
                for (int r = 0; r < 64; r++) {
                    ull v = keys[lid + (r << 5)];
                    lm = (v < lm) ? v : lm;
                }
                #pragma unroll
                for (int m = 16; m > 0; m >>= 1) {
                    ull o = shfl_xor_u64(lm, m);
                    lm = (o < lm) ? o : lm;
                }
                if (lid == 0) {
                    int bj = (int)(lm & 0xFFFFFFFFull);
                    g_eidx[gid*KK + k] = bj;
                    if (write_tail) out_tail[gid*KK + k] = (float)bj;
                    keys[bj] = KEYMAX;
                }
                __syncwarp();
            }
        }
    }
}

// ---------------------------------------------------------------- k_edge
// D[128 edges,128 ch] = A[128,416] * W^T[128,416], fp16 mma.sync m16n8k16,
// ldmatrix frags, cp.async double-buffered B, pipelined A-gen, fused LN.
extern __shared__ __align__(16) char sm_raw[];

__global__ void __launch_bounds__(256, 2) k_edge(
    const int*   __restrict__ ridx,
    const int*   __restrict__ chain,
    const float* __restrict__ Wp,
    const float* __restrict__ bp,
    const float* __restrict__ lns,
    const float* __restrict__ lno,
    float*       __restrict__ out)
{
    __shared__ int   s_gi[EPB], s_gj[EPB], s_dp[EPB];
    __shared__ float s_lns[128], s_lno[128], s_bp[16];

    int tid = threadIdx.x, wid = tid >> 5, lid = tid & 31;
    int e0  = blockIdx.x * EPB;

    uint sb = (uint)__cvta_generic_to_shared(sm_raw);
    uint Aoff[2] = { sb,           sb + 10240 };
    uint Boff[2] = { sb + 20480,   sb + 30720 };

    if (tid < EPB) {
        int edge = e0 + tid;
        int node = edge / KK;
        int bb   = node >> 11;
        int gj   = (bb << 11) + g_eidx[edge];
        s_gi[tid] = node; s_gj[tid] = gj;
        int off = ridx[node] - ridx[gj];
        s_dp[tid] = (chain[node] == chain[gj]) ? min(max(off + 32, 0), 64) : 65;
        s_lns[tid] = lns[tid]; s_lno[tid] = lno[tid];
        if (tid < 16) s_bp[tid] = bp[tid];
    }
    __syncthreads();

    int fe  = tid >> 1;     // feature row (edge)
    int fbl = tid & 1;      // 16-half half of the 32-wide chunk

    auto gen_A = [&](int c, int buf) {
        half2* dst = (half2*)(sm_raw + (buf ? 10240 : 0) + fe*ROWB + fbl*32);
        int fb = 2*c + fbl;
        if (fb == 0) {
            const float* wrow = Wp + s_dp[fe]*16;
            #pragma unroll
            for (int jj = 0; jj < 8; jj++)
                dst[jj] = __floats2half2_rn(wrow[2*jj] + s_bp[2*jj],
                                            wrow[2*jj+1] + s_bp[2*jj+1]);
        } else {
            int p = fb - 1;
            const float* pa = g_coords5 + s_gi[fe]*15 + c_pa[p]*3;
            const float* pq = g_coords5 + s_gj[fe]*15 + c_pb[p]*3;
            float dx = pa[0]-pq[0], dy = pa[1]-pq[1], dz = pa[2]-pq[2];
            float d  = __fsqrt_rn(dx*dx + dy*dy + dz*dz + 1e-6f);
            #pragma unroll
            for (int jj = 0; jj < 8; jj++) {
                float u0 = (d - (2.0f + RBF_DEL*(float)(2*jj)))   * RBF_INVS;
                float u1 = (d - (2.0f + RBF_DEL*(float)(2*jj+1))) * RBF_INVS;
                dst[jj] = __floats2half2_rn(__expf(-u0*u0), __expf(-u1*u1));
            }
        }
    };
    auto stage_B = [&](int c, int buf) {
        const char* gb = (const char*)g_wt;
        #pragma unroll
        for (int q = 0; q < 2; q++) {
            int f = tid*2 + q;
            int row = f >> 2, seg = f & 3;
            cp16(Boff[buf] + row*ROWB + seg*16, gb + row*832 + c*64 + seg*16);
        }
        CP_COMMIT();
    };

    int mw = wid >> 1, nw = wid & 1;
    int m0 = mw << 5, n0 = nw << 6;

    int arA = (lid & 7) + ((lid >> 3) & 1) * 8;
    int caA = ((lid >> 4) & 1) * 16;
    int arB = (lid & 7) + ((lid >> 4) & 1) * 8;
    int caB = ((lid >> 3) & 1) * 16;

    float acc[2][8][4];
    #pragma unroll
    for (int mt = 0; mt < 2; mt++)
        #pragma unroll
        for (int nt = 0; nt < 8; nt++)
            #pragma unroll
            for (int q = 0; q < 4; q++) acc[mt][nt][q] = 0.f;

    stage_B(0, 0);
    gen_A(0, 0);
    CP_WAIT0();
    __syncthreads();

    for (int c = 0; c < NCH; ++c) {
        int buf = c & 1, nbuf = buf ^ 1;
        if (c + 1 < NCH) stage_B(c + 1, nbuf);

        #pragma unroll
        for (int ks = 0; ks < 2; ks++) {
            int kb = ks * 32;
            uint a[2][4];
            #pragma unroll
            for (int mt = 0; mt < 2; mt++)
                ldmx4(a[mt], Aoff[buf] + (uint)(m0 + 16*mt + arA)*ROWB + caA + kb);
            uint bf[8][2];
            #pragma unroll
            for (int ntp = 0; ntp < 4; ntp++) {
                uint r[4];
                ldmx4(r, Boff[buf] + (uint)(n0 + 16*ntp + arB)*ROWB + caB + kb);
                bf[2*ntp][0]   = r[0]; bf[2*ntp][1]   = r[1];
                bf[2*ntp+1][0] = r[2]; bf[2*ntp+1][1] = r[3];
            }
            #pragma unroll
            for (int mt = 0; mt < 2; mt++)
                #pragma unroll
                for (int nt = 0; nt < 8; nt++)
                    mma16(acc[mt][nt], a[mt], bf[nt]);
        }

        if (c + 1 < NCH) gen_A(c + 1, nbuf);
        CP_WAIT0();
        __syncthreads();
    }

    // fused LayerNorm epilogue
    int lg = lid >> 2, lt = lid & 3;
    float2* red = (float2*)sm_raw;
    #pragma unroll
    for (int mt = 0; mt < 2; mt++) {
        #pragma unroll
        for (int hf = 0; hf < 2; hf++) {
            float s1 = 0.f, s2 = 0.f;
            #pragma unroll
            for (int nt = 0; nt < 8; nt++) {
                float v0 = acc[mt][nt][2*hf], v1 = acc[mt][nt][2*hf+1];
                s1 += v0 + v1; s2 += v0*v0 + v1*v1;
            }
            #pragma unroll
            for (int m = 1; m < 4; m <<= 1) {
                s1 += __shfl_xor_sync(0xFFFFFFFFu, s1, m);
                s2 += __shfl_xor_sync(0xFFFFFFFFu, s2, m);
            }
            if (lt == 0) {
                int row = m0 + 16*mt + 8*hf + lg;
                red[row*2 + nw] = make_float2(s1, s2);
            }
        }
    }
    __syncthreads();

    #pragma unroll
    for (int mt = 0; mt < 2; mt++) {
        #pragma unroll
        for (int hf = 0; hf < 2; hf++) {
            int row = m0 + 16*mt + 8*hf + lg;
            float2 r0 = red[row*2 + 0], r1 = red[row*2 + 1];
            float s1 = r0.x + r1.x, s2 = r0.y + r1.y;
            float mean = s1 * (1.0f/128.0f);
            float var  = s2 * (1.0f/128.0f) - mean*mean;
            float rstd = rsqrtf(var + 1e-5f);
            float* orow = out + (size_t)(e0 + row) * 128;
            #pragma unroll
            for (int nt = 0; nt < 8; nt++) {
                int col = n0 + nt*8 + 2*lt;
                float v0 = acc[mt][nt][2*hf], v1 = acc[mt][nt][2*hf+1];
                float2 o;
                o.x = (v0 - mean)*rstd*s_lns[col]   + s_lno[col];
                o.y = (v1 - mean)*rstd*s_lns[col+1] + s_lno[col+1];
                *(float2*)(orow + col) = o;
            }
        }
    }
}

// ----------------------------------------------------------------
extern "C" void kernel_launch(void* const* d_in, const int* in_sizes, int n_in,
                              void* d_out, int out_size)
{
    const float* X      = (const float*)d_in[0];
    const float* mask   = (const float*)d_in[1];
    const int*   ridx   = (const int*)  d_in[2];
    const int*   chain  = (const int*)  d_in[3];
    const float* W_pos  = (const float*)d_in[4];
    const float* b_pos  = (const float*)d_in[5];
    const float* W_edge = (const float*)d_in[6];
    const float* ln_s   = (const float*)d_in[7];
    const float* ln_o   = (const float*)d_in[8];
    float* out = (float*)d_out;

    int write_tail = (out_size > NEDGE*128) ? 1 : 0;
    float* tail = out + (size_t)NEDGE*128;

    int smem_bytes = 4 * 128 * ROWB;   // 40960 B

    k_init<<<(416*128 + 255)/256, 256>>>(X, W_edge);
    k_topk<<<NNODE, 256>>>(mask, tail, write_tail);
    k_edge<<<NEDGE/EPB, 256, smem_bytes>>>(ridx, chain, W_pos, b_pos,
                                           ln_s, ln_o, out);
}

// round 10
// speedup vs baseline: 2.3834x; 1.0416x over previous
#include <cuda_runtime.h>
#include <cuda_fp16.h>
#include <cstdint>

#define BB 4
#define NNN 2048
#define KK 30
#define NNODE (BB*NNN)        // 8192
#define NEDGE (NNODE*KK)      // 245760
#define EPB 128               // edges (M) per k_edge block
#define NCH 13                // K chunks of 32 (K = 416)
#define ROWB 80               // smem row stride in bytes (40 halves)
#define KEYMAX 0xFFFFFFFFFFFFFFFFull
#define NCAND 256
#define QPB 4                 // queries per k_topk block

typedef unsigned long long ull;
typedef unsigned int uint;

// scratch: __device__ globals (allocation-free rule)
__device__ float g_coords5[NNODE*15];   // N,Ca,C,O,Cb xyz per node
__device__ float g_ca[NNODE*3];
__device__ int   g_eidx[NEDGE];
__device__ __align__(16) __half g_wt[128*416];   // W^T fp16: [n][k]

// pair table: atom of node i, atom of neighbor j; N=0,Ca=1,C=2,O=3,Cb=4
__constant__ int c_pa[25] = {1, 0,2,3,4, 1,1,1,1, 0,0,0, 4,4, 3, 0,2,3,4, 2,3,4, 2,3, 2};
__constant__ int c_pb[25] = {1, 0,2,3,4, 0,2,3,4, 2,3,4, 2,3, 2, 1,1,1,1, 0,0,0, 4,4, 3};

#define RBF_DEL 1.33333333333f   // (22-2)/15
#define RBF_INVS 0.8f            // 1/sigma, sigma = 1.25

// ---------------------------------------------------------------- helpers
__device__ __forceinline__ void mma16(float* d, const uint* a, const uint* b){
    asm volatile("mma.sync.aligned.m16n8k16.row.col.f32.f16.f16.f32 "
        "{%0,%1,%2,%3}, {%4,%5,%6,%7}, {%8,%9}, {%0,%1,%2,%3};"
        : "+f"(d[0]), "+f"(d[1]), "+f"(d[2]), "+f"(d[3])
        : "r"(a[0]), "r"(a[1]), "r"(a[2]), "r"(a[3]), "r"(b[0]), "r"(b[1]));
}
__device__ __forceinline__ void ldmx4(uint* r, uint addr){
    asm volatile("ldmatrix.sync.aligned.m8n8.x4.shared.b16 {%0,%1,%2,%3}, [%4];"
        : "=r"(r[0]), "=r"(r[1]), "=r"(r[2]), "=r"(r[3]) : "r"(addr));
}
__device__ __forceinline__ void cp16(uint saddr, const void* g){
    asm volatile("cp.async.cg.shared.global [%0], [%1], 16;" :: "r"(saddr), "l"(g));
}
#define CP_COMMIT() asm volatile("cp.async.commit_group;" ::: "memory")
#define CP_WAIT0()  asm volatile("cp.async.wait_group 0;" ::: "memory")

__device__ __forceinline__ ull shfl_xor_u64(ull v, int m){
    uint lo = (uint)v, hi = (uint)(v >> 32);
    lo = __shfl_xor_sync(0xFFFFFFFFu, lo, m);
    hi = __shfl_xor_sync(0xFFFFFFFFu, hi, m);
    return ((ull)hi << 32) | lo;
}

// ---------------------------------------------------------------- k_init
__global__ void k_init(const float* __restrict__ X, const float* __restrict__ We)
{
    int idx = blockIdx.x * blockDim.x + threadIdx.x;
    if (idx < 416*128) {
        int n = idx / 416, k = idx - n*416;
        g_wt[idx] = __float2half(We[k*128 + n]);
    }
    if (idx < NNODE) {
        const float* x = X + idx*12;
        float Nx=x[0],  Ny=x[1],  Nz=x[2];
        float Cax=x[3], Cay=x[4], Caz=x[5];
        float Cx=x[6],  Cy=x[7],  Cz=x[8];
        float Ox=x[9],  Oy=x[10], Oz=x[11];
        float bx=Cax-Nx, by=Cay-Ny, bz=Caz-Nz;
        float cx=Cx-Cax, cy=Cy-Cay, cz=Cz-Caz;
        float ax = by*cz - bz*cy;
        float ay = bz*cx - bx*cz;
        float az = bx*cy - by*cx;
        float Cbx = -0.58273431f*ax + 0.56802827f*bx - 0.54067466f*cx + Cax;
        float Cby = -0.58273431f*ay + 0.56802827f*by - 0.54067466f*cy + Cay;
        float Cbz = -0.58273431f*az + 0.56802827f*bz - 0.54067466f*cz + Caz;
        float* o = g_coords5 + idx*15;
        o[0]=Nx;   o[1]=Ny;   o[2]=Nz;
        o[3]=Cax;  o[4]=Cay;  o[5]=Caz;
        o[6]=Cx;   o[7]=Cy;   o[8]=Cz;
        o[9]=Ox;   o[10]=Oy;  o[11]=Oz;
        o[12]=Cbx; o[13]=Cby; o[14]=Cbz;
        g_ca[idx*3+0]=Cax; g_ca[idx*3+1]=Cay; g_ca[idx*3+2]=Caz;
    }
}

// ---------------------------------------------------------------- k_topk
// exact ascending top-30, histogram select; QPB queries share one smem-staged
// Ca/mask copy (4x less L2 traffic). No key array: candidates from registers.
__global__ void __launch_bounds__(256) k_topk(
    const float* __restrict__ mask,
    float* __restrict__ out_tail,
    int write_tail)
{
    __shared__ float s_ca[NNN*3];      // 24 KB
    __shared__ float s_m[NNN];         // 8 KB
    __shared__ uint  s_hist[1024];     // 4 KB
    __shared__ ull   s_cand[NCAND];    // 2 KB (aliased as wred[8] in fallback)
    __shared__ float fred[8];
    __shared__ uint  s_wtot[8], s_wex[8];
    __shared__ int   s_B, s_cnt;
    __shared__ ull   s_last;

    int tid = threadIdx.x;
    int lid = tid & 31, wid = tid >> 5;

    const int bpB = NNN / QPB;                 // 512 blocks per batch
    int b  = blockIdx.x / bpB;
    int q0 = (blockIdx.x - b*bpB) * QPB;       // first local query node

    const float* cab = g_ca + (size_t)(b << 11) * 3;
    const float* mb  = mask + (b << 11);

    // stage batch Ca + mask once
    for (int t = tid; t < NNN*3; t += 256) s_ca[t] = cab[t];
    for (int t = tid; t < NNN;   t += 256) s_m[t]  = mb[t];
    __syncthreads();

    for (int q = 0; q < QPB; q++) {
        int qn  = q0 + q;                      // local node index
        int gid = (b << 11) + qn;
        float cix = s_ca[qn*3+0], ciy = s_ca[qn*3+1], ciz = s_ca[qn*3+2];
        float mi  = s_m[qn];

        // zero histogram + counter
        #pragma unroll
        for (int r = 0; r < 4; r++) s_hist[tid + (r << 8)] = 0;
        if (tid == 0) s_cnt = 0;
        __syncthreads();

        // distances from smem; row max
        float Dr[8], m2r[8];
        float lmax = 0.f;
        #pragma unroll
        for (int r = 0; r < 8; r++) {
            int j = tid + (r << 8);
            float dx = s_ca[j*3+0]-cix, dy = s_ca[j*3+1]-ciy, dz = s_ca[j*3+2]-ciz;
            float m2 = mi * s_m[j];
            float D  = m2 * __fsqrt_rn(dx*dx + dy*dy + dz*dz + 1e-6f);
            Dr[r] = D; m2r[r] = m2;
            lmax = fmaxf(lmax, D);
        }
        #pragma unroll
        for (int m = 16; m > 0; m >>= 1)
            lmax = fmaxf(lmax, __shfl_xor_sync(0xFFFFFFFFu, lmax, m));
        if (lid == 0) fred[wid] = lmax;
        __syncthreads();
        float Dmax = fred[0];
        #pragma unroll
        for (int w = 1; w < 8; w++) Dmax = fmaxf(Dmax, fred[w]);

        // adjust + pack keys + histogram
        ull  keyr[8];
        uint binr[8];
        #pragma unroll
        for (int r = 0; r < 8; r++) {
            float D = Dr[r];
            if (m2r[r] != 1.0f) D = D + (1.0f - m2r[r]) * Dmax;
            keyr[r] = ((ull)__float_as_uint(D) << 32) | (uint)(tid + (r << 8));
            uint bn = (uint)fminf(D * 25.6f, 1023.0f);
            binr[r] = bn;
            atomicAdd(&s_hist[bn], 1u);
        }
        __syncthreads();

        // block scan over 1024 bins -> bin B where cum count crosses KK
        uint c4[4];
        #pragma unroll
        for (int i = 0; i < 4; i++) c4[i] = s_hist[tid*4 + i];
        uint s = c4[0] + c4[1] + c4[2] + c4[3];
        uint inc = s;
        #pragma unroll
        for (int m = 1; m < 32; m <<= 1) {
            uint o = __shfl_up_sync(0xFFFFFFFFu, inc, m);
            if (lid >= m) inc += o;
        }
        if (lid == 31) s_wtot[wid] = inc;
        __syncthreads();
        if (tid == 0) {
            uint ex = 0;
            #pragma unroll
            for (int w = 0; w < 8; w++) { s_wex[w] = ex; ex += s_wtot[w]; }
        }
        __syncthreads();
        {
            uint ex = s_wex[wid] + (inc - s);
            if (ex < KK && ex + s >= KK) {
                uint cum = ex;
                #pragma unroll
                for (int i = 0; i < 4; i++) {
                    if (cum + c4[i] >= KK) { s_B = tid*4 + i; break; }
                    cum += c4[i];
                }
            }
        }
        __syncthreads();
        int B = s_B;

        // compaction
        #pragma unroll
        for (int r = 0; r < 8; r++) {
            if ((int)binr[r] <= B) {
                int pos = atomicAdd(&s_cnt, 1);
                if (pos < NCAND) s_cand[pos] = keyr[r];
            }
        }
        __syncthreads();
        int cnt = s_cnt;

        if (cnt <= NCAND) {
            // rank-select finish
            if (tid < cnt) {
                ull x = s_cand[tid];
                int rank = 0;
                for (int j = 0; j < cnt; j++)
                    rank += (s_cand[j] < x) ? 1 : 0;
                if (rank < KK) {
                    int bj = (int)(x & 0xFFFFFFFFull);
                    g_eidx[gid*KK + rank] = bj;
                    if (write_tail) out_tail[gid*KK + rank] = (float)bj;
                }
            }
        } else {
            // fallback: 30-round monotonic extraction from registers
            // (k-th min = min over unique keys strictly greater than last)
            ull last = 0;
            for (int k = 0; k < KK; k++) {
                ull lm = KEYMAX;
                #pragma unroll
                for (int r = 0; r < 8; r++) {
                    bool ok = (k == 0) ? true : (keyr[r] > last);
                    if (ok && keyr[r] < lm) lm = keyr[r];
                }
                #pragma unroll
                for (int m = 16; m > 0; m >>= 1) {
                    ull o = shfl_xor_u64(lm, m);
                    lm = (o < lm) ? o : lm;
                }
                if (lid == 0) s_cand[wid] = lm;   // 8 warp minima
                __syncthreads();
                if (tid == 0) {
                    ull best = s_cand[0];
                    #pragma unroll
                    for (int w = 1; w < 8; w++)
                        best = (s_cand[w] < best) ? s_cand[w] : best;
                    s_last = best;
                    int bj = (int)(best & 0xFFFFFFFFull);
                    g_eidx[gid*KK + k] = bj;
                    if (write_tail) out_tail[gid*KK + k] = (float)bj;
                }
                __syncthreads();
                last = s_last;
            }
        }
        __syncthreads();
    }
}

// ---------------------------------------------------------------- k_edge
// D[128 edges,128 ch] = A[128,416] * W^T[128,416], fp16 mma.sync m16n8k16,
// ldmatrix frags, cp.async double-buffered B, pipelined A-gen, fused LN.
extern __shared__ __align__(16) char sm_raw[];

__global__ void __launch_bounds__(256, 2) k_edge(
    const int*   __restrict__ ridx,
    const int*   __restrict__ chain,
    const float* __restrict__ Wp,
    const float* __restrict__ bp,
    const float* __restrict__ lns,
    const float* __restrict__ lno,
    float*       __restrict__ out)
{
    __shared__ int   s_gi[EPB], s_gj[EPB], s_dp[EPB];
    __shared__ float s_lns[128], s_lno[128], s_bp[16];

    int tid = threadIdx.x, wid = tid >> 5, lid = tid & 31;
    int e0  = blockIdx.x * EPB;

    uint sb = (uint)__cvta_generic_to_shared(sm_raw);
    uint Aoff[2] = { sb,           sb + 10240 };
    uint Boff[2] = { sb + 20480,   sb + 30720 };

    if (tid < EPB) {
        int edge = e0 + tid;
        int node = edge / KK;
        int bb   = node >> 11;
        int gj   = (bb << 11) + g_eidx[edge];
        s_gi[tid] = node; s_gj[tid] = gj;
        int off = ridx[node] - ridx[gj];
        s_dp[tid] = (chain[node] == chain[gj]) ? min(max(off + 32, 0), 64) : 65;
        s_lns[tid] = lns[tid]; s_lno[tid] = lno[tid];
        if (tid < 16) s_bp[tid] = bp[tid];
    }
    __syncthreads();

    int fe  = tid >> 1;
    int fbl = tid & 1;

    auto gen_A = [&](int c, int buf) {
        half2* dst = (half2*)(sm_raw + (buf ? 10240 : 0) + fe*ROWB + fbl*32);
        int fb = 2*c + fbl;
        if (fb == 0) {
            const float* wrow = Wp + s_dp[fe]*16;
            #pragma unroll
            for (int jj = 0; jj < 8; jj++)
                dst[jj] = __floats2half2_rn(wrow[2*jj] + s_bp[2*jj],
                                            wrow[2*jj+1] + s_bp[2*jj+1]);
        } else {
            int p = fb - 1;
            const float* pa = g_coords5 + s_gi[fe]*15 + c_pa[p]*3;
            const float* pq = g_coords5 + s_gj[fe]*15 + c_pb[p]*3;
            float dx = pa[0]-pq[0], dy = pa[1]-pq[1], dz = pa[2]-pq[2];
            float d  = __fsqrt_rn(dx*dx + dy*dy + dz*dz + 1e-6f);
            #pragma unroll
            for (int jj = 0; jj < 8; jj++) {
                float u0 = (d - (2.0f + RBF_DEL*(float)(2*jj)))   * RBF_INVS;
                float u1 = (d - (2.0f + RBF_DEL*(float)(2*jj+1))) * RBF_INVS;
                dst[jj] = __floats2half2_rn(__expf(-u0*u0), __expf(-u1*u1));
            }
        }
    };
    auto stage_B = [&](int c, int buf) {
        const char* gb = (const char*)g_wt;
        #pragma unroll
        for (int q = 0; q < 2; q++) {
            int f = tid*2 + q;
            int row = f >> 2, seg = f & 3;
            cp16(Boff[buf] + row*ROWB + seg*16, gb + row*832 + c*64 + seg*16);
        }
        CP_COMMIT();
    };

    int mw = wid >> 1, nw = wid & 1;
    int m0 = mw << 5, n0 = nw << 6;

    int arA = (lid & 7) + ((lid >> 3) & 1) * 8;
    int caA = ((lid >> 4) & 1) * 16;
    int arB = (lid & 7) + ((lid >> 4) & 1) * 8;
    int caB = ((lid >> 3) & 1) * 16;

    float acc[2][8][4];
    #pragma unroll
    for (int mt = 0; mt < 2; mt++)
        #pragma unroll
        for (int nt = 0; nt < 8; nt++)
            #pragma unroll
            for (int q = 0; q < 4; q++) acc[mt][nt][q] = 0.f;

    stage_B(0, 0);
    gen_A(0, 0);
    CP_WAIT0();
    __syncthreads();

    for (int c = 0; c < NCH; ++c) {
        int buf = c & 1, nbuf = buf ^ 1;
        if (c + 1 < NCH) stage_B(c + 1, nbuf);

        #pragma unroll
        for (int ks = 0; ks < 2; ks++) {
            int kb = ks * 32;
            uint a[2][4];
            #pragma unroll
            for (int mt = 0; mt < 2; mt++)
                ldmx4(a[mt], Aoff[buf] + (uint)(m0 + 16*mt + arA)*ROWB + caA + kb);
            uint bf[8][2];
            #pragma unroll
            for (int ntp = 0; ntp < 4; ntp++) {
                uint r[4];
                ldmx4(r, Boff[buf] + (uint)(n0 + 16*ntp + arB)*ROWB + caB + kb);
                bf[2*ntp][0]   = r[0]; bf[2*ntp][1]   = r[1];
                bf[2*ntp+1][0] = r[2]; bf[2*ntp+1][1] = r[3];
            }
            #pragma unroll
            for (int mt = 0; mt < 2; mt++)
                #pragma unroll
                for (int nt = 0; nt < 8; nt++)
                    mma16(acc[mt][nt], a[mt], bf[nt]);
        }

        if (c + 1 < NCH) gen_A(c + 1, nbuf);
        CP_WAIT0();
        __syncthreads();
    }

    // fused LayerNorm epilogue
    int lg = lid >> 2, lt = lid & 3;
    float2* red = (float2*)sm_raw;
    #pragma unroll
    for (int mt = 0; mt < 2; mt++) {
        #pragma unroll
        for (int hf = 0; hf < 2; hf++) {
            float s1 = 0.f, s2 = 0.f;
            #pragma unroll
            for (int nt = 0; nt < 8; nt++) {
                float v0 = acc[mt][nt][2*hf], v1 = acc[mt][nt][2*hf+1];
                s1 += v0 + v1; s2 += v0*v0 + v1*v1;
            }
            #pragma unroll
            for (int m = 1; m < 4; m <<= 1) {
                s1 += __shfl_xor_sync(0xFFFFFFFFu, s1, m);
                s2 += __shfl_xor_sync(0xFFFFFFFFu, s2, m);
            }
            if (lt == 0) {
                int row = m0 + 16*mt + 8*hf + lg;
                red[row*2 + nw] = make_float2(s1, s2);
            }
        }
    }
    __syncthreads();

    #pragma unroll
    for (int mt = 0; mt < 2; mt++) {
        #pragma unroll
        for (int hf = 0; hf < 2; hf++) {
            int row = m0 + 16*mt + 8*hf + lg;
            float2 r0 = red[row*2 + 0], r1 = red[row*2 + 1];
            float s1 = r0.x + r1.x, s2 = r0.y + r1.y;
            float mean = s1 * (1.0f/128.0f);
            float var  = s2 * (1.0f/128.0f) - mean*mean;
            float rstd = rsqrtf(var + 1e-5f);
            float* orow = out + (size_t)(e0 + row) * 128;
            #pragma unroll
            for (int nt = 0; nt < 8; nt++) {
                int col = n0 + nt*8 + 2*lt;
                float v0 = acc[mt][nt][2*hf], v1 = acc[mt][nt][2*hf+1];
                float2 o;
                o.x = (v0 - mean)*rstd*s_lns[col]   + s_lno[col];
                o.y = (v1 - mean)*rstd*s_lns[col+1] + s_lno[col+1];
                *(float2*)(orow + col) = o;
            }
        }
    }
}

// ----------------------------------------------------------------
extern "C" void kernel_launch(void* const* d_in, const int* in_sizes, int n_in,
                              void* d_out, int out_size)
{
    const float* X      = (const float*)d_in[0];
    const float* mask   = (const float*)d_in[1];
    const int*   ridx   = (const int*)  d_in[2];
    const int*   chain  = (const int*)  d_in[3];
    const float* W_pos  = (const float*)d_in[4];
    const float* b_pos  = (const float*)d_in[5];
    const float* W_edge = (const float*)d_in[6];
    const float* ln_s   = (const float*)d_in[7];
    const float* ln_o   = (const float*)d_in[8];
    float* out = (float*)d_out;

    int write_tail = (out_size > NEDGE*128) ? 1 : 0;
    float* tail = out + (size_t)NEDGE*128;

    int smem_bytes = 4 * 128 * ROWB;   // 40960 B

    k_init<<<(416*128 + 255)/256, 256>>>(X, W_edge);
    k_topk<<<NNODE/QPB, 256>>>(mask, tail, write_tail);
    k_edge<<<NEDGE/EPB, 256, smem_bytes>>>(ridx, chain, W_pos, b_pos,
                                           ln_s, ln_o, out);
}